// round 12
// baseline (speedup 1.0000x reference)
#include <cuda_runtime.h>
#include <math_constants.h>

#define NT 32
#define NQ 256
#define NNODE 8192
#define DD 128
#define CHN 32
#define KK 16
#define NBF 8
#define BB 4
#define CAP 4096      // padded per-batch capacity
#define HBINS 1024    // d2_bits >> 21
#define CANDCAP 128

__device__ float g_nfext[NNODE * DD];
__device__ float g_cxp[BB * CAP], g_cyp[BB * CAP], g_czp[BB * CAP];  // padded SoA (INF pads)
__device__ float g_tf[DD];
__device__ int   g_range[BB + 1];
__device__ float g_coef[6 * CHN];
__device__ float g_partial[NT * NQ * 6];

static __device__ __forceinline__ float3 qrot(float w, float x, float y, float z, float3 v) {
    float uvx = y * v.z - z * v.y;
    float uvy = z * v.x - x * v.z;
    float uvz = x * v.y - y * v.x;
    float wx = y * uvz - z * uvy;
    float wy = z * uvx - x * uvz;
    float wz = x * uvy - y * uvx;
    float3 r;
    r.x = v.x + 2.f * (w * uvx + wx);
    r.y = v.y + 2.f * (w * uvy + wy);
    r.z = v.z + 2.f * (w * uvz + wz);
    return r;
}

// ---- misc: tf, ranges, folded coefs ------------------------------------------
__global__ void k_misc(const float* __restrict__ te, const float* __restrict__ Wtime,
                       const int* __restrict__ nbatch,
                       const float* __restrict__ wp_lin, const float* __restrict__ Wv_lin,
                       const float* __restrict__ wp_ang, const float* __restrict__ Wv_ang) {
    int tid = threadIdx.x;  // 192
    if (tid < DD) {
        float acc = 0.f;
        for (int k = 0; k < DD; k++) acc = fmaf(te[k], Wtime[k * DD + tid], acc);
        g_tf[tid] = 1.f + acc;
    }
    if (tid <= BB) {
        int lo = 0, hi = NNODE;
        if (tid == BB) lo = NNODE;
        else {
            while (lo < hi) { int m = (lo + hi) >> 1; if (nbatch[m] < tid) lo = m + 1; else hi = m; }
        }
        g_range[tid] = lo;
    }
    {
        int g = tid / CHN, c = tid % CHN;  // g in 0..5
        const float* wp = (g < 3) ? wp_lin : wp_ang;
        const float* Wv = (g < 3) ? Wv_lin : Wv_ang;
        int gg = g % 3;
        int wrow = gg * CHN + c;
        float s = 0.f;
        for (int o = 0; o < CHN; o++) s += Wv[wrow * CHN + o];
        g_coef[g * CHN + c] = wp[(2 + gg) * CHN + c] * s * (1.f / (float)CHN);
    }
}

// ---- padded SoA coords (bit-exact copies; INF pads) --------------------------
__global__ void k_coord(const float* __restrict__ ncoord) {
    int idx = blockIdx.x * 256 + threadIdx.x;   // 16384 slots
    int b = idx >> 12, i = idx & (CAP - 1);
    int lo = g_range[b];
    int n = g_range[b + 1] - lo;
    float vx = CUDART_INF_F, vy = CUDART_INF_F, vz = CUDART_INF_F;
    if (i < n) {
        vx = ncoord[(lo + i) * 3 + 0];
        vy = ncoord[(lo + i) * 3 + 1];
        vz = ncoord[(lo + i) * 3 + 2];
    }
    g_cxp[idx] = vx; g_cyp[idx] = vy; g_czp[idx] = vz;
}

// ---- nf_ext GEMM (smem-tiled, 32 nodes/block) --------------------------------
#define PN 32
__global__ __launch_bounds__(256) void k_pre(
    const float* __restrict__ nf, const float* __restrict__ Wext) {
    __shared__ float sW[32 * DD];
    __shared__ float snf[PN][33];
    int tid = threadIdx.x;
    int b = blockIdx.x;
    int cg = tid & 31;
    int ng = tid >> 5;
    float acc[4][4];
#pragma unroll
    for (int i = 0; i < 4; i++)
#pragma unroll
        for (int j = 0; j < 4; j++) acc[i][j] = 0.f;
    for (int kt = 0; kt < DD; kt += 32) {
        for (int idx = tid; idx < 32 * DD; idx += 256)
            sW[idx] = Wext[(kt + (idx >> 7)) * DD + (idx & 127)];
        for (int idx = tid; idx < PN * 32; idx += 256)
            snf[idx >> 5][idx & 31] = nf[(b * PN + (idx >> 5)) * DD + kt + (idx & 31)];
        __syncthreads();
#pragma unroll 8
        for (int kk = 0; kk < 32; kk++) {
            float4 w = *(const float4*)&sW[kk * DD + cg * 4];
            float a0 = snf[ng * 4 + 0][kk];
            float a1 = snf[ng * 4 + 1][kk];
            float a2 = snf[ng * 4 + 2][kk];
            float a3 = snf[ng * 4 + 3][kk];
            acc[0][0] = fmaf(a0, w.x, acc[0][0]); acc[0][1] = fmaf(a0, w.y, acc[0][1]);
            acc[0][2] = fmaf(a0, w.z, acc[0][2]); acc[0][3] = fmaf(a0, w.w, acc[0][3]);
            acc[1][0] = fmaf(a1, w.x, acc[1][0]); acc[1][1] = fmaf(a1, w.y, acc[1][1]);
            acc[1][2] = fmaf(a1, w.z, acc[1][2]); acc[1][3] = fmaf(a1, w.w, acc[1][3]);
            acc[2][0] = fmaf(a2, w.x, acc[2][0]); acc[2][1] = fmaf(a2, w.y, acc[2][1]);
            acc[2][2] = fmaf(a2, w.z, acc[2][2]); acc[2][3] = fmaf(a2, w.w, acc[2][3]);
            acc[3][0] = fmaf(a3, w.x, acc[3][0]); acc[3][1] = fmaf(a3, w.y, acc[3][1]);
            acc[3][2] = fmaf(a3, w.z, acc[3][2]); acc[3][3] = fmaf(a3, w.w, acc[3][3]);
        }
        __syncthreads();
    }
#pragma unroll
    for (int i = 0; i < 4; i++) {
        float4 o = { acc[i][0], acc[i][1], acc[i][2], acc[i][3] };
        *(float4*)&g_nfext[(b * PN + ng * 4 + i) * DD + cg * 4] = o;
    }
}

// ---- main: one block per (query, transform); prefiltered radix-select --------
__global__ __launch_bounds__(256) void k_main(
    const float* __restrict__ T, const float* __restrict__ qwgt,
    const float* __restrict__ qf, const float* __restrict__ qcrd,
    const float* __restrict__ Wrbf, const int* __restrict__ qbatch) {
    __shared__ unsigned hist[HBINS];
    __shared__ float sdov[CAP - 2048];
    __shared__ unsigned long long cand[CANDCAP];
    __shared__ float swmin16[16];
    __shared__ float sM;
    __shared__ float srbf[KK * NBF];
    __shared__ float sfld2[2][DD];
    __shared__ float sfield[DD];
    __shared__ int ssel[KK];
    __shared__ float sd2sel[KK];
    __shared__ unsigned swarp[8];
    __shared__ unsigned scnt;
    __shared__ int sB;

    int qi = blockIdx.x, t = blockIdx.y, tid = threadIdx.x;
    int lane = tid & 31, wid = tid >> 5;

    int b = qbatch[qi];
    int lo = g_range[b];
    int n = g_range[b + 1] - lo;
    if (n > CAP) n = CAP;
    int n_pad = (n + 3) & ~3;
    float3 qc0 = { qcrd[qi * 3 + 0], qcrd[qi * 3 + 1], qcrd[qi * 3 + 2] };

    float qw0 = T[t * 7 + 0], qx = T[t * 7 + 1], qy = T[t * 7 + 2], qz = T[t * 7 + 3];
    float3 p = qrot(qw0, qx, qy, qz, qc0);
    p.x += T[t * 7 + 4]; p.y += T[t * 7 + 5]; p.z += T[t * 7 + 6];

    // zero hist / cand / scnt
    ((uint4*)hist)[tid] = make_uint4(0u, 0u, 0u, 0u);
    if (tid < CANDCAP) cand[tid] = ~0ull;
    if (tid == 0) scnt = 0u;

    // distance pass: float4 over padded SoA; first 2048 in regs, rest in sdov
    const float* cx = g_cxp + b * CAP;
    const float* cy = g_cyp + b * CAP;
    const float* cz = g_czp + b * CAP;
    float d2v[8];
    float tmin = CUDART_INF_F;
#pragma unroll
    for (int g = 0; g < 2; g++) {
        int i0 = tid * 4 + 1024 * g;
        if (i0 < n_pad) {
            float4 X = *(const float4*)(cx + i0);
            float4 Y = *(const float4*)(cy + i0);
            float4 Z = *(const float4*)(cz + i0);
            float dx, dy, dz;
            dx = p.x - X.x; dy = p.y - Y.x; dz = p.z - Z.x;
            d2v[g * 4 + 0] = dx * dx + dy * dy + dz * dz;
            dx = p.x - X.y; dy = p.y - Y.y; dz = p.z - Z.y;
            d2v[g * 4 + 1] = dx * dx + dy * dy + dz * dz;
            dx = p.x - X.z; dy = p.y - Y.z; dz = p.z - Z.z;
            d2v[g * 4 + 2] = dx * dx + dy * dy + dz * dz;
            dx = p.x - X.w; dy = p.y - Y.w; dz = p.z - Z.w;
            d2v[g * 4 + 3] = dx * dx + dy * dy + dz * dz;
            tmin = fminf(tmin, fminf(fminf(d2v[g * 4 + 0], d2v[g * 4 + 1]),
                                     fminf(d2v[g * 4 + 2], d2v[g * 4 + 3])));
        } else {
            d2v[g * 4 + 0] = CUDART_INF_F; d2v[g * 4 + 1] = CUDART_INF_F;
            d2v[g * 4 + 2] = CUDART_INF_F; d2v[g * 4 + 3] = CUDART_INF_F;
        }
    }
    for (int i0 = 2048 + tid * 4; i0 < n_pad; i0 += 1024) {
        float4 X = *(const float4*)(cx + i0);
        float4 Y = *(const float4*)(cy + i0);
        float4 Z = *(const float4*)(cz + i0);
        float4 D;
        float dx, dy, dz;
        dx = p.x - X.x; dy = p.y - Y.x; dz = p.z - Z.x; D.x = dx * dx + dy * dy + dz * dz;
        dx = p.x - X.y; dy = p.y - Y.y; dz = p.z - Z.y; D.y = dx * dx + dy * dy + dz * dz;
        dx = p.x - X.z; dy = p.y - Y.z; dz = p.z - Z.z; D.z = dx * dx + dy * dy + dz * dz;
        dx = p.x - X.w; dy = p.y - Y.w; dz = p.z - Z.w; D.w = dx * dx + dy * dy + dz * dz;
        *(float4*)&sdov[i0 - 2048] = D;
        tmin = fminf(tmin, fminf(fminf(D.x, D.y), fminf(D.z, D.w)));
    }

    // half-warp minima -> prefilter bound M (max of 16 minima => >=16 elems <= M)
    {
        float v = tmin;
#pragma unroll
        for (int o = 1; o < 16; o <<= 1)
            v = fminf(v, __shfl_xor_sync(0xffffffffu, v, o, 16));
        if ((lane & 15) == 0) swmin16[wid * 2 + (lane >> 4)] = v;
    }
    __syncthreads();
    if (tid == 0) {
        float M = swmin16[0];
#pragma unroll
        for (int j = 1; j < 16; j++) M = fmaxf(M, swmin16[j]);
        sM = M;
    }
    __syncthreads();
    float M = sM;

    // sparse histogram: only elements <= M (~tens per block)
#pragma unroll
    for (int j = 0; j < 8; j++)
        if (d2v[j] <= M) atomicAdd(&hist[__float_as_uint(d2v[j]) >> 21], 1u);
    for (int i0 = 2048 + tid * 4; i0 < n_pad; i0 += 1024) {
#pragma unroll
        for (int k = 0; k < 4; k++) {
            float d2 = sdov[i0 - 2048 + k];
            if (d2 <= M) atomicAdd(&hist[__float_as_uint(d2) >> 21], 1u);
        }
    }
    __syncthreads();

    // scan 1024 bins (4/thread) -> threshold bin sB (rank KK); B == bin(d16)
    uint4 h = ((const uint4*)hist)[tid];
    unsigned hb[4] = { h.x, h.y, h.z, h.w };
    unsigned mysum = hb[0] + hb[1] + hb[2] + hb[3];
    unsigned inc = mysum;
#pragma unroll
    for (int o = 1; o < 32; o <<= 1) {
        unsigned v = __shfl_up_sync(0xffffffffu, inc, o);
        if (lane >= o) inc += v;
    }
    if (lane == 31) swarp[wid] = inc;
    __syncthreads();
    unsigned base = 0;
    for (int w = 0; w < wid; w++) base += swarp[w];
    unsigned excl = base + inc - mysum;
    if (excl < KK && excl + mysum >= KK) {
        unsigned cum = excl;
#pragma unroll
        for (int j = 0; j < 4; j++) {
            cum += hb[j];
            if (cum >= KK) { sB = tid * 4 + j; break; }
        }
    }
    __syncthreads();
    unsigned B = (unsigned)sB;

    // collect ALL elements with bin <= B (INF pads: bin 1020 > B, self-excluded)
#pragma unroll
    for (int j = 0; j < 8; j++) {
        if ((__float_as_uint(d2v[j]) >> 21) <= B) {
            int i = tid * 4 + 1024 * (j >> 2) + (j & 3);
            unsigned pos = atomicAdd(&scnt, 1u);
            if (pos < CANDCAP)
                cand[pos] = ((unsigned long long)__float_as_uint(d2v[j]) << 32) | (unsigned)i;
        }
    }
    for (int i0 = 2048 + tid * 4; i0 < n_pad; i0 += 1024) {
#pragma unroll
        for (int k = 0; k < 4; k++) {
            float d2 = sdov[i0 - 2048 + k];
            if ((__float_as_uint(d2) >> 21) <= B) {
                unsigned pos = atomicAdd(&scnt, 1u);
                if (pos < CANDCAP)
                    cand[pos] = ((unsigned long long)__float_as_uint(d2) << 32) | (unsigned)(i0 + k);
            }
        }
    }
    __syncthreads();

    // exact rank via LDS-broadcast compares (unique keys)
    int m = scnt < CANDCAP ? (int)scnt : CANDCAP;
    {
        int ci = wid * 16 + (lane & 15);
        if (lane < 16 && ci < m) {
            unsigned long long my = cand[ci];
            int r = 0;
            for (int j = 0; j < m; j++)
                r += (cand[j] < my);
            if (r < KK) {
                ssel[r] = (int)(unsigned)my;
                sd2sel[r] = __uint_as_float((unsigned)(my >> 32));
            }
        }
    }
    __syncthreads();

    // rbf basis
    if (tid < KK * NBF) {
        int k = tid >> 3, bb2 = tid & 7;
        float d = sqrtf(fmaxf(sd2sel[k], 1e-12f));
        float e = d - (3.0f / 7.0f) * (float)bb2;
        srbf[tid] = expf(-4.f * e * e);
    }
    __syncthreads();

    // field: 256 threads, 8 k's each
    {
        int d = tid & 127, h2 = tid >> 7;
        float acc = 0.f;
#pragma unroll
        for (int k2 = 0; k2 < 8; k2++) {
            int k = h2 * 8 + k2;
            int gi = lo + ssel[k];
            float coef = 0.f;
#pragma unroll
            for (int bb2 = 0; bb2 < NBF; bb2++)
                coef = fmaf(srbf[k * NBF + bb2], Wrbf[bb2 * DD + d], coef);
            acc = fmaf(coef, g_nfext[gi * DD + d], acc);
        }
        sfld2[h2][d] = acc;
    }
    __syncthreads();
    if (tid < DD)
        sfield[tid] = (sfld2[0][tid] + sfld2[1][tid]) * g_tf[tid];
    __syncthreads();

    // dtp + per-(t,q) partial (warp0)
    if (tid < CHN) {
        float e_s  = qf[qi * DD + tid];
        float3 v0 = { qf[qi * DD + CHN + 3 * tid + 0],
                      qf[qi * DD + CHN + 3 * tid + 1],
                      qf[qi * DD + CHN + 3 * tid + 2] };
        float e_al = g_coef[tid];           float e_bl = g_coef[CHN + tid];     float e_el = g_coef[2 * CHN + tid];
        float e_aa = g_coef[3 * CHN + tid]; float e_ba = g_coef[4 * CHN + tid]; float e_ea = g_coef[5 * CHN + tid];
        float3 v = qrot(qw0, qx, qy, qz, v0);
        float ttv = sfield[tid];
        float3 u = { sfield[CHN + 3 * tid + 0], sfield[CHN + 3 * tid + 1], sfield[CHN + 3 * tid + 2] };
        float3 cr = { v.y * u.z - v.z * u.y, v.z * u.x - v.x * u.z, v.x * u.y - v.y * u.x };
        float lvx = e_al * e_s * u.x + e_bl * ttv * v.x + e_el * cr.x;
        float lvy = e_al * e_s * u.y + e_bl * ttv * v.y + e_el * cr.y;
        float lvz = e_al * e_s * u.z + e_bl * ttv * v.z + e_el * cr.z;
        float avx = e_aa * e_s * u.x + e_ba * ttv * v.x + e_ea * cr.x;
        float avy = e_aa * e_s * u.y + e_ba * ttv * v.y + e_ea * cr.y;
        float avz = e_aa * e_s * u.z + e_ba * ttv * v.z + e_ea * cr.z;
#pragma unroll
        for (int o = 16; o > 0; o >>= 1) {
            lvx += __shfl_down_sync(0xffffffffu, lvx, o);
            lvy += __shfl_down_sync(0xffffffffu, lvy, o);
            lvz += __shfl_down_sync(0xffffffffu, lvz, o);
            avx += __shfl_down_sync(0xffffffffu, avx, o);
            avy += __shfl_down_sync(0xffffffffu, avy, o);
            avz += __shfl_down_sync(0xffffffffu, avz, o);
        }
        if (tid == 0) {
            float3 lv = qrot(qw0, -qx, -qy, -qz, make_float3(lvx, lvy, lvz));
            float3 av = qrot(qw0, -qx, -qy, -qz, make_float3(avx, avy, avz));
            float3 orb = { qc0.y * lv.z - qc0.z * lv.y,
                           qc0.z * lv.x - qc0.x * lv.z,
                           qc0.x * lv.y - qc0.y * lv.x };
            float e_w = qwgt[qi];
            const float inv_s2 = 0.70710678118654752440f;
            float* pp = &g_partial[(t * NQ + qi) * 6];
            pp[0] = e_w * (orb.x + av.x * inv_s2);
            pp[1] = e_w * (orb.y + av.y * inv_s2);
            pp[2] = e_w * (orb.z + av.z * inv_s2);
            pp[3] = e_w * lv.x;
            pp[4] = e_w * lv.y;
            pp[5] = e_w * lv.z;
        }
    }
}

// ---- deterministic final reduction over queries ------------------------------
__global__ void k_reduce(float* __restrict__ out) {
    int t = blockIdx.x, tid = threadIdx.x;
    int lane = tid & 31, wid = tid >> 5;
    float a[6];
    const float* pp = &g_partial[(t * NQ + tid) * 6];
#pragma unroll
    for (int j = 0; j < 6; j++) a[j] = pp[j];
#pragma unroll
    for (int j = 0; j < 6; j++) {
        for (int o = 16; o > 0; o >>= 1)
            a[j] += __shfl_down_sync(0xffffffffu, a[j], o);
    }
    __shared__ float sw[8][6];
    if (lane == 0) {
#pragma unroll
        for (int j = 0; j < 6; j++) sw[wid][j] = a[j];
    }
    __syncthreads();
    if (tid == 0) {
        float r[6] = {0, 0, 0, 0, 0, 0};
        for (int w2 = 0; w2 < 8; w2++)
            for (int j = 0; j < 6; j++) r[j] += sw[w2][j];
        out[t * 3 + 0] = r[0];
        out[t * 3 + 1] = r[1];
        out[t * 3 + 2] = r[2];
        out[NT * 3 + t * 3 + 0] = r[3];
        out[NT * 3 + t * 3 + 1] = r[4];
        out[NT * 3 + t * 3 + 2] = r[5];
    }
}

extern "C" void kernel_launch(void* const* d_in, const int* in_sizes, int n_in,
                              void* d_out, int out_size) {
    const float* T      = (const float*)d_in[0];
    const float* qwgt   = (const float*)d_in[1];
    const float* qfeat  = (const float*)d_in[2];
    const float* qcoord = (const float*)d_in[3];
    const float* nfeat  = (const float*)d_in[4];
    const float* ncoord = (const float*)d_in[5];
    const float* temb   = (const float*)d_in[6];
    const float* Wext   = (const float*)d_in[7];
    const float* Wrbf   = (const float*)d_in[8];
    const float* Wtime  = (const float*)d_in[9];
    const float* wp_lin = (const float*)d_in[10];
    const float* Wv_lin = (const float*)d_in[12];
    const float* wp_ang = (const float*)d_in[13];
    const float* Wv_ang = (const float*)d_in[15];
    const int*   qbatch = (const int*)d_in[16];
    const int*   nbatch = (const int*)d_in[17];
    float* out = (float*)d_out;

    k_misc<<<1, 192>>>(temb, Wtime, nbatch, wp_lin, Wv_lin, wp_ang, Wv_ang);
    k_pre<<<NNODE / PN, 256>>>(nfeat, Wext);
    k_coord<<<BB * CAP / 256, 256>>>(ncoord);
    k_main<<<dim3(NQ, NT), 256>>>(T, qwgt, qfeat, qcoord, Wrbf, qbatch);
    k_reduce<<<NT, NQ>>>(out);
}

// round 13
// speedup vs baseline: 1.1730x; 1.1730x over previous
#include <cuda_runtime.h>
#include <math_constants.h>

#define NT 32
#define NQ 256
#define NNODE 8192
#define DD 128
#define CHN 32
#define KK 16
#define NBF 8
#define BB 4
#define CAP 4096
#define HBINS 1024
#define CANDCAP 128
#define PN 32

__device__ float g_nfext[NNODE * DD];
__device__ float g_cxp[BB * CAP], g_cyp[BB * CAP], g_czp[BB * CAP];  // padded SoA (INF pads)
__device__ float g_tf[DD];
__device__ int   g_range[BB + 1];
__device__ float g_coef[6 * CHN];
__device__ float g_partial[NT * NQ * 6];

static __device__ __forceinline__ float3 qrot(float w, float x, float y, float z, float3 v) {
    float uvx = y * v.z - z * v.y;
    float uvy = z * v.x - x * v.z;
    float uvz = x * v.y - y * v.x;
    float wx = y * uvz - z * uvy;
    float wy = z * uvx - x * uvz;
    float wz = x * uvy - y * uvx;
    float3 r;
    r.x = v.x + 2.f * (w * uvx + wx);
    r.y = v.y + 2.f * (w * uvy + wy);
    r.z = v.z + 2.f * (w * uvz + wz);
    return r;
}

__global__ void k_nop() {}

// ---- fused precompute: GEMM blocks + coord-pad blocks + misc block -----------
__global__ __launch_bounds__(256) void k_pre(
    const float* __restrict__ nf, const float* __restrict__ Wext,
    const float* __restrict__ ncoord,
    const float* __restrict__ te, const float* __restrict__ Wtime,
    const int* __restrict__ nbatch,
    const float* __restrict__ wp_lin, const float* __restrict__ Wv_lin,
    const float* __restrict__ wp_ang, const float* __restrict__ Wv_ang) {
    int tid = threadIdx.x;
    int blk = blockIdx.x;

    if (blk >= NNODE / PN) {
        if (blk < NNODE / PN + 64) {
            // coord padding blocks: 64 blocks x 256 slots = 16384
            int idx = (blk - NNODE / PN) * 256 + tid;
            int b = idx >> 12, i = idx & (CAP - 1);
            // local binary searches for [lo, hi) of batch b (no cross-block dep)
            int lo = 0, hi = NNODE;
            if (b > 0) {
                int l = 0, h = NNODE;
                while (l < h) { int m2 = (l + h) >> 1; if (nbatch[m2] < b) l = m2 + 1; else h = m2; }
                lo = l;
            }
            {
                int l = lo, h = NNODE;
                while (l < h) { int m2 = (l + h) >> 1; if (nbatch[m2] < b + 1) l = m2 + 1; else h = m2; }
                hi = l;
            }
            int n = hi - lo;
            float vx = CUDART_INF_F, vy = CUDART_INF_F, vz = CUDART_INF_F;
            if (i < n) {
                vx = ncoord[(lo + i) * 3 + 0];
                vy = ncoord[(lo + i) * 3 + 1];
                vz = ncoord[(lo + i) * 3 + 2];
            }
            g_cxp[idx] = vx; g_cyp[idx] = vy; g_czp[idx] = vz;
        } else {
            // misc block
            if (tid < DD) {
                float acc = 0.f;
                for (int k = 0; k < DD; k++) acc = fmaf(te[k], Wtime[k * DD + tid], acc);
                g_tf[tid] = 1.f + acc;
            }
            if (tid <= BB) {
                int l = 0, h = NNODE;
                if (tid == BB) l = NNODE;
                else {
                    while (l < h) { int m2 = (l + h) >> 1; if (nbatch[m2] < tid) l = m2 + 1; else h = m2; }
                }
                g_range[tid] = l;
            }
            if (tid < 192) {
                int g = tid / CHN, c = tid % CHN;
                const float* wp = (g < 3) ? wp_lin : wp_ang;
                const float* Wv = (g < 3) ? Wv_lin : Wv_ang;
                int gg = g % 3;
                int wrow = gg * CHN + c;
                float s = 0.f;
                for (int o = 0; o < CHN; o++) s += Wv[wrow * CHN + o];
                g_coef[g * CHN + c] = wp[(2 + gg) * CHN + c] * s * (1.f / (float)CHN);
            }
        }
        return;
    }

    // GEMM blocks
    __shared__ float sW[32 * DD];
    __shared__ float snf[PN][33];
    int b = blk;
    int cg = tid & 31;
    int ng = tid >> 5;
    float acc[4][4];
#pragma unroll
    for (int i = 0; i < 4; i++)
#pragma unroll
        for (int j = 0; j < 4; j++) acc[i][j] = 0.f;
    for (int kt = 0; kt < DD; kt += 32) {
        for (int idx = tid; idx < 32 * DD; idx += 256)
            sW[idx] = Wext[(kt + (idx >> 7)) * DD + (idx & 127)];
        for (int idx = tid; idx < PN * 32; idx += 256)
            snf[idx >> 5][idx & 31] = nf[(b * PN + (idx >> 5)) * DD + kt + (idx & 31)];
        __syncthreads();
#pragma unroll 8
        for (int kk = 0; kk < 32; kk++) {
            float4 w = *(const float4*)&sW[kk * DD + cg * 4];
            float a0 = snf[ng * 4 + 0][kk];
            float a1 = snf[ng * 4 + 1][kk];
            float a2 = snf[ng * 4 + 2][kk];
            float a3 = snf[ng * 4 + 3][kk];
            acc[0][0] = fmaf(a0, w.x, acc[0][0]); acc[0][1] = fmaf(a0, w.y, acc[0][1]);
            acc[0][2] = fmaf(a0, w.z, acc[0][2]); acc[0][3] = fmaf(a0, w.w, acc[0][3]);
            acc[1][0] = fmaf(a1, w.x, acc[1][0]); acc[1][1] = fmaf(a1, w.y, acc[1][1]);
            acc[1][2] = fmaf(a1, w.z, acc[1][2]); acc[1][3] = fmaf(a1, w.w, acc[1][3]);
            acc[2][0] = fmaf(a2, w.x, acc[2][0]); acc[2][1] = fmaf(a2, w.y, acc[2][1]);
            acc[2][2] = fmaf(a2, w.z, acc[2][2]); acc[2][3] = fmaf(a2, w.w, acc[2][3]);
            acc[3][0] = fmaf(a3, w.x, acc[3][0]); acc[3][1] = fmaf(a3, w.y, acc[3][1]);
            acc[3][2] = fmaf(a3, w.z, acc[3][2]); acc[3][3] = fmaf(a3, w.w, acc[3][3]);
        }
        __syncthreads();
    }
#pragma unroll
    for (int i = 0; i < 4; i++) {
        float4 o = { acc[i][0], acc[i][1], acc[i][2], acc[i][3] };
        *(float4*)&g_nfext[(b * PN + ng * 4 + i) * DD + cg * 4] = o;
    }
}

// ---- main: one block per (query, transform); prefiltered radix-select --------
__global__ __launch_bounds__(256, 6) void k_main(
    const float* __restrict__ T, const float* __restrict__ qwgt,
    const float* __restrict__ qf, const float* __restrict__ qcrd,
    const float* __restrict__ Wrbf, const int* __restrict__ qbatch) {
    __shared__ unsigned hist[HBINS];
    __shared__ unsigned long long cand[CANDCAP];
    __shared__ float swmin16[16];
    __shared__ float sM;
    __shared__ __align__(16) float srbf[KK * NBF];
    __shared__ float sfld2[2][DD];
    __shared__ float sfield[DD];
    __shared__ int ssel[KK];
    __shared__ float sd2sel[KK];
    __shared__ unsigned swarp[8];
    __shared__ unsigned scnt;
    __shared__ int sB;

    int qi = blockIdx.x, t = blockIdx.y, tid = threadIdx.x;
    int lane = tid & 31, wid = tid >> 5;

    int b = qbatch[qi];
    int lo = g_range[b];
    int n = g_range[b + 1] - lo;
    if (n > CAP) n = CAP;
    int n_pad = (n + 3) & ~3;
    float3 qc0 = { qcrd[qi * 3 + 0], qcrd[qi * 3 + 1], qcrd[qi * 3 + 2] };

    float qw0 = T[t * 7 + 0], qx = T[t * 7 + 1], qy = T[t * 7 + 2], qz = T[t * 7 + 3];
    float3 p = qrot(qw0, qx, qy, qz, qc0);
    p.x += T[t * 7 + 4]; p.y += T[t * 7 + 5]; p.z += T[t * 7 + 6];

    // zero hist / cand / scnt
    ((uint4*)hist)[tid] = make_uint4(0u, 0u, 0u, 0u);
    if (tid < CANDCAP) cand[tid] = ~0ull;
    if (tid == 0) scnt = 0u;

    const float* cx = g_cxp + b * CAP;
    const float* cy = g_cyp + b * CAP;
    const float* cz = g_czp + b * CAP;

    // distance pass: first 2048 in registers; overflow recomputed later
    float d2v[8];
    float tmin = CUDART_INF_F;
#pragma unroll
    for (int g = 0; g < 2; g++) {
        int i0 = tid * 4 + 1024 * g;
        float4 X = *(const float4*)(cx + i0);
        float4 Y = *(const float4*)(cy + i0);
        float4 Z = *(const float4*)(cz + i0);
        float dx, dy, dz;
        dx = p.x - X.x; dy = p.y - Y.x; dz = p.z - Z.x;
        d2v[g * 4 + 0] = dx * dx + dy * dy + dz * dz;
        dx = p.x - X.y; dy = p.y - Y.y; dz = p.z - Z.y;
        d2v[g * 4 + 1] = dx * dx + dy * dy + dz * dz;
        dx = p.x - X.z; dy = p.y - Y.z; dz = p.z - Z.z;
        d2v[g * 4 + 2] = dx * dx + dy * dy + dz * dz;
        dx = p.x - X.w; dy = p.y - Y.w; dz = p.z - Z.w;
        d2v[g * 4 + 3] = dx * dx + dy * dy + dz * dz;
        tmin = fminf(tmin, fminf(fminf(d2v[g * 4 + 0], d2v[g * 4 + 1]),
                                 fminf(d2v[g * 4 + 2], d2v[g * 4 + 3])));
    }
    for (int i0 = 2048 + tid * 4; i0 < n_pad; i0 += 1024) {
        float4 X = *(const float4*)(cx + i0);
        float4 Y = *(const float4*)(cy + i0);
        float4 Z = *(const float4*)(cz + i0);
        float dx, dy, dz, d2;
        dx = p.x - X.x; dy = p.y - Y.x; dz = p.z - Z.x; d2 = dx * dx + dy * dy + dz * dz;
        tmin = fminf(tmin, d2);
        dx = p.x - X.y; dy = p.y - Y.y; dz = p.z - Z.y; d2 = dx * dx + dy * dy + dz * dz;
        tmin = fminf(tmin, d2);
        dx = p.x - X.z; dy = p.y - Y.z; dz = p.z - Z.z; d2 = dx * dx + dy * dy + dz * dz;
        tmin = fminf(tmin, d2);
        dx = p.x - X.w; dy = p.y - Y.w; dz = p.z - Z.w; d2 = dx * dx + dy * dy + dz * dz;
        tmin = fminf(tmin, d2);
    }

    // half-warp minima -> prefilter bound M (>=16 elements <= M)
    {
        float v = tmin;
#pragma unroll
        for (int o = 1; o < 16; o <<= 1)
            v = fminf(v, __shfl_xor_sync(0xffffffffu, v, o, 16));
        if ((lane & 15) == 0) swmin16[wid * 2 + (lane >> 4)] = v;
    }
    __syncthreads();
    if (tid == 0) {
        float M = swmin16[0];
#pragma unroll
        for (int j = 1; j < 16; j++) M = fmaxf(M, swmin16[j]);
        sM = M;
    }
    __syncthreads();
    float M = sM;

    // sparse histogram: only elements <= M
#pragma unroll
    for (int j = 0; j < 8; j++)
        if (d2v[j] <= M) atomicAdd(&hist[__float_as_uint(d2v[j]) >> 21], 1u);
    for (int i0 = 2048 + tid * 4; i0 < n_pad; i0 += 1024) {
        float4 X = *(const float4*)(cx + i0);
        float4 Y = *(const float4*)(cy + i0);
        float4 Z = *(const float4*)(cz + i0);
        float dx, dy, dz, d2;
        dx = p.x - X.x; dy = p.y - Y.x; dz = p.z - Z.x; d2 = dx * dx + dy * dy + dz * dz;
        if (d2 <= M) atomicAdd(&hist[__float_as_uint(d2) >> 21], 1u);
        dx = p.x - X.y; dy = p.y - Y.y; dz = p.z - Z.y; d2 = dx * dx + dy * dy + dz * dz;
        if (d2 <= M) atomicAdd(&hist[__float_as_uint(d2) >> 21], 1u);
        dx = p.x - X.z; dy = p.y - Y.z; dz = p.z - Z.z; d2 = dx * dx + dy * dy + dz * dz;
        if (d2 <= M) atomicAdd(&hist[__float_as_uint(d2) >> 21], 1u);
        dx = p.x - X.w; dy = p.y - Y.w; dz = p.z - Z.w; d2 = dx * dx + dy * dy + dz * dz;
        if (d2 <= M) atomicAdd(&hist[__float_as_uint(d2) >> 21], 1u);
    }
    __syncthreads();

    // scan 1024 bins -> threshold bin sB (rank KK)
    uint4 h = ((const uint4*)hist)[tid];
    unsigned hb[4] = { h.x, h.y, h.z, h.w };
    unsigned mysum = hb[0] + hb[1] + hb[2] + hb[3];
    unsigned inc = mysum;
#pragma unroll
    for (int o = 1; o < 32; o <<= 1) {
        unsigned v = __shfl_up_sync(0xffffffffu, inc, o);
        if (lane >= o) inc += v;
    }
    if (lane == 31) swarp[wid] = inc;
    __syncthreads();
    unsigned base = 0;
    for (int w = 0; w < wid; w++) base += swarp[w];
    unsigned excl = base + inc - mysum;
    if (excl < KK && excl + mysum >= KK) {
        unsigned cum = excl;
#pragma unroll
        for (int j = 0; j < 4; j++) {
            cum += hb[j];
            if (cum >= KK) { sB = tid * 4 + j; break; }
        }
    }
    __syncthreads();
    unsigned B = (unsigned)sB;

    // collect: all elements with bin <= B (INF pads self-excluded)
#pragma unroll
    for (int j = 0; j < 8; j++) {
        if ((__float_as_uint(d2v[j]) >> 21) <= B) {
            int i = tid * 4 + 1024 * (j >> 2) + (j & 3);
            unsigned pos = atomicAdd(&scnt, 1u);
            if (pos < CANDCAP)
                cand[pos] = ((unsigned long long)__float_as_uint(d2v[j]) << 32) | (unsigned)i;
        }
    }
    for (int i0 = 2048 + tid * 4; i0 < n_pad; i0 += 1024) {
        float4 X = *(const float4*)(cx + i0);
        float4 Y = *(const float4*)(cy + i0);
        float4 Z = *(const float4*)(cz + i0);
        float dvals[4];
        float dx, dy, dz;
        dx = p.x - X.x; dy = p.y - Y.x; dz = p.z - Z.x; dvals[0] = dx * dx + dy * dy + dz * dz;
        dx = p.x - X.y; dy = p.y - Y.y; dz = p.z - Z.y; dvals[1] = dx * dx + dy * dy + dz * dz;
        dx = p.x - X.z; dy = p.y - Y.z; dz = p.z - Z.z; dvals[2] = dx * dx + dy * dy + dz * dz;
        dx = p.x - X.w; dy = p.y - Y.w; dz = p.z - Z.w; dvals[3] = dx * dx + dy * dy + dz * dz;
#pragma unroll
        for (int k = 0; k < 4; k++) {
            if ((__float_as_uint(dvals[k]) >> 21) <= B) {
                unsigned pos = atomicAdd(&scnt, 1u);
                if (pos < CANDCAP)
                    cand[pos] = ((unsigned long long)__float_as_uint(dvals[k]) << 32) | (unsigned)(i0 + k);
            }
        }
    }
    __syncthreads();

    // exact rank via LDS-broadcast compares (unique keys)
    int m = scnt < CANDCAP ? (int)scnt : CANDCAP;
    {
        int ci = wid * 16 + (lane & 15);
        if (lane < 16 && ci < m) {
            unsigned long long my = cand[ci];
            int r = 0;
            for (int j = 0; j < m; j++)
                r += (cand[j] < my);
            if (r < KK) {
                ssel[r] = (int)(unsigned)my;
                sd2sel[r] = __uint_as_float((unsigned)(my >> 32));
            }
        }
    }
    __syncthreads();

    // rbf basis
    if (tid < KK * NBF) {
        int k = tid >> 3, bb2 = tid & 7;
        float d = sqrtf(fmaxf(sd2sel[k], 1e-12f));
        float e = d - (3.0f / 7.0f) * (float)bb2;
        srbf[tid] = expf(-4.f * e * e);
    }
    __syncthreads();

    // field: 256 threads, 8 k's each; Wrbf slice hoisted to registers
    {
        int d = tid & 127, h2 = tid >> 7;
        float W0 = Wrbf[0 * DD + d], W1 = Wrbf[1 * DD + d];
        float W2 = Wrbf[2 * DD + d], W3 = Wrbf[3 * DD + d];
        float W4 = Wrbf[4 * DD + d], W5 = Wrbf[5 * DD + d];
        float W6 = Wrbf[6 * DD + d], W7 = Wrbf[7 * DD + d];
        float acc = 0.f;
#pragma unroll
        for (int k2 = 0; k2 < 8; k2++) {
            int k = h2 * 8 + k2;
            float4 r0 = *(const float4*)&srbf[k * NBF];
            float4 r1 = *(const float4*)&srbf[k * NBF + 4];
            float coef = 0.f;
            coef = fmaf(r0.x, W0, coef);
            coef = fmaf(r0.y, W1, coef);
            coef = fmaf(r0.z, W2, coef);
            coef = fmaf(r0.w, W3, coef);
            coef = fmaf(r1.x, W4, coef);
            coef = fmaf(r1.y, W5, coef);
            coef = fmaf(r1.z, W6, coef);
            coef = fmaf(r1.w, W7, coef);
            acc = fmaf(coef, g_nfext[(lo + ssel[k]) * DD + d], acc);
        }
        sfld2[h2][d] = acc;
    }
    __syncthreads();
    if (tid < DD)
        sfield[tid] = (sfld2[0][tid] + sfld2[1][tid]) * g_tf[tid];
    __syncthreads();

    // dtp + per-(t,q) partial (warp0)
    if (tid < CHN) {
        float e_s  = qf[qi * DD + tid];
        float3 v0 = { qf[qi * DD + CHN + 3 * tid + 0],
                      qf[qi * DD + CHN + 3 * tid + 1],
                      qf[qi * DD + CHN + 3 * tid + 2] };
        float e_al = g_coef[tid];           float e_bl = g_coef[CHN + tid];     float e_el = g_coef[2 * CHN + tid];
        float e_aa = g_coef[3 * CHN + tid]; float e_ba = g_coef[4 * CHN + tid]; float e_ea = g_coef[5 * CHN + tid];
        float3 v = qrot(qw0, qx, qy, qz, v0);
        float ttv = sfield[tid];
        float3 u = { sfield[CHN + 3 * tid + 0], sfield[CHN + 3 * tid + 1], sfield[CHN + 3 * tid + 2] };
        float3 cr = { v.y * u.z - v.z * u.y, v.z * u.x - v.x * u.z, v.x * u.y - v.y * u.x };
        float lvx = e_al * e_s * u.x + e_bl * ttv * v.x + e_el * cr.x;
        float lvy = e_al * e_s * u.y + e_bl * ttv * v.y + e_el * cr.y;
        float lvz = e_al * e_s * u.z + e_bl * ttv * v.z + e_el * cr.z;
        float avx = e_aa * e_s * u.x + e_ba * ttv * v.x + e_ea * cr.x;
        float avy = e_aa * e_s * u.y + e_ba * ttv * v.y + e_ea * cr.y;
        float avz = e_aa * e_s * u.z + e_ba * ttv * v.z + e_ea * cr.z;
#pragma unroll
        for (int o = 16; o > 0; o >>= 1) {
            lvx += __shfl_down_sync(0xffffffffu, lvx, o);
            lvy += __shfl_down_sync(0xffffffffu, lvy, o);
            lvz += __shfl_down_sync(0xffffffffu, lvz, o);
            avx += __shfl_down_sync(0xffffffffu, avx, o);
            avy += __shfl_down_sync(0xffffffffu, avy, o);
            avz += __shfl_down_sync(0xffffffffu, avz, o);
        }
        if (tid == 0) {
            float3 lv = qrot(qw0, -qx, -qy, -qz, make_float3(lvx, lvy, lvz));
            float3 av = qrot(qw0, -qx, -qy, -qz, make_float3(avx, avy, avz));
            float3 orb = { qc0.y * lv.z - qc0.z * lv.y,
                           qc0.z * lv.x - qc0.x * lv.z,
                           qc0.x * lv.y - qc0.y * lv.x };
            float e_w = qwgt[qi];
            const float inv_s2 = 0.70710678118654752440f;
            float* pp = &g_partial[(t * NQ + qi) * 6];
            pp[0] = e_w * (orb.x + av.x * inv_s2);
            pp[1] = e_w * (orb.y + av.y * inv_s2);
            pp[2] = e_w * (orb.z + av.z * inv_s2);
            pp[3] = e_w * lv.x;
            pp[4] = e_w * lv.y;
            pp[5] = e_w * lv.z;
        }
    }
}

// ---- deterministic final reduction over queries ------------------------------
__global__ void k_reduce(float* __restrict__ out) {
    int t = blockIdx.x, tid = threadIdx.x;
    int lane = tid & 31, wid = tid >> 5;
    float a[6];
    const float* pp = &g_partial[(t * NQ + tid) * 6];
#pragma unroll
    for (int j = 0; j < 6; j++) a[j] = pp[j];
#pragma unroll
    for (int j = 0; j < 6; j++) {
        for (int o = 16; o > 0; o >>= 1)
            a[j] += __shfl_down_sync(0xffffffffu, a[j], o);
    }
    __shared__ float sw[8][6];
    if (lane == 0) {
#pragma unroll
        for (int j = 0; j < 6; j++) sw[wid][j] = a[j];
    }
    __syncthreads();
    if (tid == 0) {
        float r[6] = {0, 0, 0, 0, 0, 0};
        for (int w2 = 0; w2 < 8; w2++)
            for (int j = 0; j < 6; j++) r[j] += sw[w2][j];
        out[t * 3 + 0] = r[0];
        out[t * 3 + 1] = r[1];
        out[t * 3 + 2] = r[2];
        out[NT * 3 + t * 3 + 0] = r[3];
        out[NT * 3 + t * 3 + 1] = r[4];
        out[NT * 3 + t * 3 + 2] = r[5];
    }
}

extern "C" void kernel_launch(void* const* d_in, const int* in_sizes, int n_in,
                              void* d_out, int out_size) {
    const float* T      = (const float*)d_in[0];
    const float* qwgt   = (const float*)d_in[1];
    const float* qfeat  = (const float*)d_in[2];
    const float* qcoord = (const float*)d_in[3];
    const float* nfeat  = (const float*)d_in[4];
    const float* ncoord = (const float*)d_in[5];
    const float* temb   = (const float*)d_in[6];
    const float* Wext   = (const float*)d_in[7];
    const float* Wrbf   = (const float*)d_in[8];
    const float* Wtime  = (const float*)d_in[9];
    const float* wp_lin = (const float*)d_in[10];
    const float* Wv_lin = (const float*)d_in[12];
    const float* wp_ang = (const float*)d_in[13];
    const float* Wv_ang = (const float*)d_in[15];
    const int*   qbatch = (const int*)d_in[16];
    const int*   nbatch = (const int*)d_in[17];
    float* out = (float*)d_out;

    k_pre<<<NNODE / PN + 64 + 1, 256>>>(nfeat, Wext, ncoord, temb, Wtime, nbatch,
                                        wp_lin, Wv_lin, wp_ang, Wv_ang);
    k_main<<<dim3(NQ, NT), 256>>>(T, qwgt, qfeat, qcoord, Wrbf, qbatch);
    k_reduce<<<NT, NQ>>>(out);
    k_nop<<<1, 1>>>();   // keep k_main at ncu capture slot 6
}

// round 14
// speedup vs baseline: 1.2405x; 1.0575x over previous
#include <cuda_runtime.h>
#include <math_constants.h>

#define NT 32
#define NQ 256
#define NNODE 8192
#define DD 128
#define CHN 32
#define KK 16
#define NBF 8
#define BB 4
#define CAP 4096
#define CANDCAP 192
#define PN 32

__device__ float g_nfext[NNODE * DD];
__device__ float g_cxp[BB * CAP], g_cyp[BB * CAP], g_czp[BB * CAP];  // padded SoA (INF pads)
__device__ float g_tf[DD];
__device__ int   g_range[BB + 1];
__device__ float g_coef[6 * CHN];
__device__ float g_partial[NT * NQ * 6];

static __device__ __forceinline__ float3 qrot(float w, float x, float y, float z, float3 v) {
    float uvx = y * v.z - z * v.y;
    float uvy = z * v.x - x * v.z;
    float uvz = x * v.y - y * v.x;
    float wx = y * uvz - z * uvy;
    float wy = z * uvx - x * uvz;
    float wz = x * uvy - y * uvx;
    float3 r;
    r.x = v.x + 2.f * (w * uvx + wx);
    r.y = v.y + 2.f * (w * uvy + wy);
    r.z = v.z + 2.f * (w * uvz + wz);
    return r;
}

// ---- fused precompute: GEMM blocks + coord-pad blocks + misc block -----------
__global__ __launch_bounds__(256) void k_pre(
    const float* __restrict__ nf, const float* __restrict__ Wext,
    const float* __restrict__ ncoord,
    const float* __restrict__ te, const float* __restrict__ Wtime,
    const int* __restrict__ nbatch,
    const float* __restrict__ wp_lin, const float* __restrict__ Wv_lin,
    const float* __restrict__ wp_ang, const float* __restrict__ Wv_ang) {
    int tid = threadIdx.x;
    int blk = blockIdx.x;

    if (blk >= NNODE / PN) {
        if (blk < NNODE / PN + 64) {
            // coord padding blocks: 64 blocks x 256 slots = 16384
            int idx = (blk - NNODE / PN) * 256 + tid;
            int b = idx >> 12, i = idx & (CAP - 1);
            int lo = 0;
            if (b > 0) {
                int l = 0, h = NNODE;
                while (l < h) { int m2 = (l + h) >> 1; if (nbatch[m2] < b) l = m2 + 1; else h = m2; }
                lo = l;
            }
            int hi;
            {
                int l = lo, h = NNODE;
                while (l < h) { int m2 = (l + h) >> 1; if (nbatch[m2] < b + 1) l = m2 + 1; else h = m2; }
                hi = l;
            }
            int n = hi - lo;
            float vx = CUDART_INF_F, vy = CUDART_INF_F, vz = CUDART_INF_F;
            if (i < n) {
                vx = ncoord[(lo + i) * 3 + 0];
                vy = ncoord[(lo + i) * 3 + 1];
                vz = ncoord[(lo + i) * 3 + 2];
            }
            g_cxp[idx] = vx; g_cyp[idx] = vy; g_czp[idx] = vz;
        } else {
            // misc block
            if (tid < DD) {
                float acc = 0.f;
                for (int k = 0; k < DD; k++) acc = fmaf(te[k], Wtime[k * DD + tid], acc);
                g_tf[tid] = 1.f + acc;
            }
            if (tid <= BB) {
                int l = 0, h = NNODE;
                if (tid == BB) l = NNODE;
                else {
                    while (l < h) { int m2 = (l + h) >> 1; if (nbatch[m2] < tid) l = m2 + 1; else h = m2; }
                }
                g_range[tid] = l;
            }
            if (tid < 192) {
                int g = tid / CHN, c = tid % CHN;
                const float* wp = (g < 3) ? wp_lin : wp_ang;
                const float* Wv = (g < 3) ? Wv_lin : Wv_ang;
                int gg = g % 3;
                int wrow = gg * CHN + c;
                float s = 0.f;
                for (int o = 0; o < CHN; o++) s += Wv[wrow * CHN + o];
                g_coef[g * CHN + c] = wp[(2 + gg) * CHN + c] * s * (1.f / (float)CHN);
            }
        }
        return;
    }

    // GEMM blocks
    __shared__ float sW[32 * DD];
    __shared__ float snf[PN][33];
    int b = blk;
    int cg = tid & 31;
    int ng = tid >> 5;
    float acc[4][4];
#pragma unroll
    for (int i = 0; i < 4; i++)
#pragma unroll
        for (int j = 0; j < 4; j++) acc[i][j] = 0.f;
    for (int kt = 0; kt < DD; kt += 32) {
        for (int idx = tid; idx < 32 * DD; idx += 256)
            sW[idx] = Wext[(kt + (idx >> 7)) * DD + (idx & 127)];
        for (int idx = tid; idx < PN * 32; idx += 256)
            snf[idx >> 5][idx & 31] = nf[(b * PN + (idx >> 5)) * DD + kt + (idx & 31)];
        __syncthreads();
#pragma unroll 8
        for (int kk = 0; kk < 32; kk++) {
            float4 w = *(const float4*)&sW[kk * DD + cg * 4];
            float a0 = snf[ng * 4 + 0][kk];
            float a1 = snf[ng * 4 + 1][kk];
            float a2 = snf[ng * 4 + 2][kk];
            float a3 = snf[ng * 4 + 3][kk];
            acc[0][0] = fmaf(a0, w.x, acc[0][0]); acc[0][1] = fmaf(a0, w.y, acc[0][1]);
            acc[0][2] = fmaf(a0, w.z, acc[0][2]); acc[0][3] = fmaf(a0, w.w, acc[0][3]);
            acc[1][0] = fmaf(a1, w.x, acc[1][0]); acc[1][1] = fmaf(a1, w.y, acc[1][1]);
            acc[1][2] = fmaf(a1, w.z, acc[1][2]); acc[1][3] = fmaf(a1, w.w, acc[1][3]);
            acc[2][0] = fmaf(a2, w.x, acc[2][0]); acc[2][1] = fmaf(a2, w.y, acc[2][1]);
            acc[2][2] = fmaf(a2, w.z, acc[2][2]); acc[2][3] = fmaf(a2, w.w, acc[2][3]);
            acc[3][0] = fmaf(a3, w.x, acc[3][0]); acc[3][1] = fmaf(a3, w.y, acc[3][1]);
            acc[3][2] = fmaf(a3, w.z, acc[3][2]); acc[3][3] = fmaf(a3, w.w, acc[3][3]);
        }
        __syncthreads();
    }
#pragma unroll
    for (int i = 0; i < 4; i++) {
        float4 o = { acc[i][0], acc[i][1], acc[i][2], acc[i][3] };
        *(float4*)&g_nfext[(b * PN + ng * 4 + i) * DD + cg * 4] = o;
    }
}

// ---- main: one block per (query, transform); 2nd-min prefilter select --------
__global__ __launch_bounds__(256, 6) void k_main(
    const float* __restrict__ T, const float* __restrict__ qwgt,
    const float* __restrict__ qf, const float* __restrict__ qcrd,
    const float* __restrict__ Wrbf, const int* __restrict__ qbatch) {
    __shared__ unsigned long long cand[CANDCAP];
    __shared__ float sw2[8];
    __shared__ float sM;
    __shared__ __align__(16) float srbf[KK * NBF];
    __shared__ float sfld2[2][DD];
    __shared__ float sfield[DD];
    __shared__ int ssel[KK];
    __shared__ float sd2sel[KK];
    __shared__ unsigned scnt;

    int qi = blockIdx.x, t = blockIdx.y, tid = threadIdx.x;
    int lane = tid & 31, wid = tid >> 5;

    int b = qbatch[qi];
    int lo = g_range[b];
    int n = g_range[b + 1] - lo;
    if (n > CAP) n = CAP;
    int n_pad = (n + 3) & ~3;
    float3 qc0 = { qcrd[qi * 3 + 0], qcrd[qi * 3 + 1], qcrd[qi * 3 + 2] };

    float qw0 = T[t * 7 + 0], qx = T[t * 7 + 1], qy = T[t * 7 + 2], qz = T[t * 7 + 3];
    float3 p = qrot(qw0, qx, qy, qz, qc0);
    p.x += T[t * 7 + 4]; p.y += T[t * 7 + 5]; p.z += T[t * 7 + 6];

    if (tid == 0) scnt = 0u;

    const float* cx = g_cxp + b * CAP;
    const float* cy = g_cyp + b * CAP;
    const float* cz = g_czp + b * CAP;

    // distance pass: first 2048 in registers; overflow recomputed later
    float d2v[8];
    float tmin = CUDART_INF_F;
#pragma unroll
    for (int g = 0; g < 2; g++) {
        int i0 = tid * 4 + 1024 * g;
        float4 X = *(const float4*)(cx + i0);
        float4 Y = *(const float4*)(cy + i0);
        float4 Z = *(const float4*)(cz + i0);
        float dx, dy, dz;
        dx = p.x - X.x; dy = p.y - Y.x; dz = p.z - Z.x;
        d2v[g * 4 + 0] = dx * dx + dy * dy + dz * dz;
        dx = p.x - X.y; dy = p.y - Y.y; dz = p.z - Z.y;
        d2v[g * 4 + 1] = dx * dx + dy * dy + dz * dz;
        dx = p.x - X.z; dy = p.y - Y.z; dz = p.z - Z.z;
        d2v[g * 4 + 2] = dx * dx + dy * dy + dz * dz;
        dx = p.x - X.w; dy = p.y - Y.w; dz = p.z - Z.w;
        d2v[g * 4 + 3] = dx * dx + dy * dy + dz * dz;
        tmin = fminf(tmin, fminf(fminf(d2v[g * 4 + 0], d2v[g * 4 + 1]),
                                 fminf(d2v[g * 4 + 2], d2v[g * 4 + 3])));
    }
    for (int i0 = 2048 + tid * 4; i0 < n_pad; i0 += 1024) {
        float4 X = *(const float4*)(cx + i0);
        float4 Y = *(const float4*)(cy + i0);
        float4 Z = *(const float4*)(cz + i0);
        float dx, dy, dz, d2;
        dx = p.x - X.x; dy = p.y - Y.x; dz = p.z - Z.x; d2 = dx * dx + dy * dy + dz * dz;
        tmin = fminf(tmin, d2);
        dx = p.x - X.y; dy = p.y - Y.y; dz = p.z - Z.y; d2 = dx * dx + dy * dy + dz * dz;
        tmin = fminf(tmin, d2);
        dx = p.x - X.z; dy = p.y - Y.z; dz = p.z - Z.z; d2 = dx * dx + dy * dy + dz * dz;
        tmin = fminf(tmin, d2);
        dx = p.x - X.w; dy = p.y - Y.w; dz = p.z - Z.w; d2 = dx * dx + dy * dy + dz * dz;
        tmin = fminf(tmin, d2);
    }

    // per-warp 2nd-smallest lane-min -> bound M (>=2 distinct elements per warp <= w2)
    {
        float v = tmin;
#pragma unroll
        for (int o = 16; o > 0; o >>= 1)
            v = fminf(v, __shfl_xor_sync(0xffffffffu, v, o));
        float m1 = v;                                   // warp min (all lanes)
        unsigned bal = __ballot_sync(0xffffffffu, tmin == m1);
        int leader = __ffs(bal) - 1;
        float vv = (lane == leader) ? CUDART_INF_F : tmin;
#pragma unroll
        for (int o = 16; o > 0; o >>= 1)
            vv = fminf(vv, __shfl_xor_sync(0xffffffffu, vv, o));
        if (lane == 0) sw2[wid] = vv;                   // warp's 2nd-smallest lane-min
    }
    __syncthreads();
    if (tid == 0) {
        float M = sw2[0];
#pragma unroll
        for (int j = 1; j < 8; j++) M = fmaxf(M, sw2[j]);
        sM = M;
    }
    __syncthreads();
    float M = sM;

    // collect: ALL elements with d2 <= M (top-16 guaranteed inside; INF pads excluded)
#pragma unroll
    for (int j = 0; j < 8; j++) {
        if (d2v[j] <= M) {
            int i = tid * 4 + 1024 * (j >> 2) + (j & 3);
            unsigned pos = atomicAdd(&scnt, 1u);
            if (pos < CANDCAP)
                cand[pos] = ((unsigned long long)__float_as_uint(d2v[j]) << 32) | (unsigned)i;
        }
    }
    for (int i0 = 2048 + tid * 4; i0 < n_pad; i0 += 1024) {
        float4 X = *(const float4*)(cx + i0);
        float4 Y = *(const float4*)(cy + i0);
        float4 Z = *(const float4*)(cz + i0);
        float dvals[4];
        float dx, dy, dz;
        dx = p.x - X.x; dy = p.y - Y.x; dz = p.z - Z.x; dvals[0] = dx * dx + dy * dy + dz * dz;
        dx = p.x - X.y; dy = p.y - Y.y; dz = p.z - Z.y; dvals[1] = dx * dx + dy * dy + dz * dz;
        dx = p.x - X.z; dy = p.y - Y.z; dz = p.z - Z.z; dvals[2] = dx * dx + dy * dy + dz * dz;
        dx = p.x - X.w; dy = p.y - Y.w; dz = p.z - Z.w; dvals[3] = dx * dx + dy * dy + dz * dz;
#pragma unroll
        for (int k = 0; k < 4; k++) {
            if (dvals[k] <= M) {
                unsigned pos = atomicAdd(&scnt, 1u);
                if (pos < CANDCAP)
                    cand[pos] = ((unsigned long long)__float_as_uint(dvals[k]) << 32) | (unsigned)(i0 + k);
            }
        }
    }
    __syncthreads();

    // exact rank via LDS-broadcast compares (unique keys)
    int m = scnt < CANDCAP ? (int)scnt : CANDCAP;
    if (tid < m) {
        unsigned long long my = cand[tid];
        int r = 0;
        for (int j = 0; j < m; j++)
            r += (cand[j] < my);
        if (r < KK) {
            ssel[r] = (int)(unsigned)my;
            sd2sel[r] = __uint_as_float((unsigned)(my >> 32));
        }
    }
    __syncthreads();

    // rbf basis
    if (tid < KK * NBF) {
        int k = tid >> 3, bb2 = tid & 7;
        float d = sqrtf(fmaxf(sd2sel[k], 1e-12f));
        float e = d - (3.0f / 7.0f) * (float)bb2;
        srbf[tid] = expf(-4.f * e * e);
    }
    __syncthreads();

    // field: 256 threads, 8 k's each; Wrbf slice hoisted to registers
    {
        int d = tid & 127, h2 = tid >> 7;
        float W0 = Wrbf[0 * DD + d], W1 = Wrbf[1 * DD + d];
        float W2 = Wrbf[2 * DD + d], W3 = Wrbf[3 * DD + d];
        float W4 = Wrbf[4 * DD + d], W5 = Wrbf[5 * DD + d];
        float W6 = Wrbf[6 * DD + d], W7 = Wrbf[7 * DD + d];
        float acc = 0.f;
#pragma unroll
        for (int k2 = 0; k2 < 8; k2++) {
            int k = h2 * 8 + k2;
            float4 r0 = *(const float4*)&srbf[k * NBF];
            float4 r1 = *(const float4*)&srbf[k * NBF + 4];
            float coef = 0.f;
            coef = fmaf(r0.x, W0, coef);
            coef = fmaf(r0.y, W1, coef);
            coef = fmaf(r0.z, W2, coef);
            coef = fmaf(r0.w, W3, coef);
            coef = fmaf(r1.x, W4, coef);
            coef = fmaf(r1.y, W5, coef);
            coef = fmaf(r1.z, W6, coef);
            coef = fmaf(r1.w, W7, coef);
            acc = fmaf(coef, g_nfext[(lo + ssel[k]) * DD + d], acc);
        }
        sfld2[h2][d] = acc;
    }
    __syncthreads();
    if (tid < DD)
        sfield[tid] = (sfld2[0][tid] + sfld2[1][tid]) * g_tf[tid];
    __syncthreads();

    // dtp + per-(t,q) partial (warp0)
    if (tid < CHN) {
        float e_s  = qf[qi * DD + tid];
        float3 v0 = { qf[qi * DD + CHN + 3 * tid + 0],
                      qf[qi * DD + CHN + 3 * tid + 1],
                      qf[qi * DD + CHN + 3 * tid + 2] };
        float e_al = g_coef[tid];           float e_bl = g_coef[CHN + tid];     float e_el = g_coef[2 * CHN + tid];
        float e_aa = g_coef[3 * CHN + tid]; float e_ba = g_coef[4 * CHN + tid]; float e_ea = g_coef[5 * CHN + tid];
        float3 v = qrot(qw0, qx, qy, qz, v0);
        float ttv = sfield[tid];
        float3 u = { sfield[CHN + 3 * tid + 0], sfield[CHN + 3 * tid + 1], sfield[CHN + 3 * tid + 2] };
        float3 cr = { v.y * u.z - v.z * u.y, v.z * u.x - v.x * u.z, v.x * u.y - v.y * u.x };
        float lvx = e_al * e_s * u.x + e_bl * ttv * v.x + e_el * cr.x;
        float lvy = e_al * e_s * u.y + e_bl * ttv * v.y + e_el * cr.y;
        float lvz = e_al * e_s * u.z + e_bl * ttv * v.z + e_el * cr.z;
        float avx = e_aa * e_s * u.x + e_ba * ttv * v.x + e_ea * cr.x;
        float avy = e_aa * e_s * u.y + e_ba * ttv * v.y + e_ea * cr.y;
        float avz = e_aa * e_s * u.z + e_ba * ttv * v.z + e_ea * cr.z;
#pragma unroll
        for (int o = 16; o > 0; o >>= 1) {
            lvx += __shfl_down_sync(0xffffffffu, lvx, o);
            lvy += __shfl_down_sync(0xffffffffu, lvy, o);
            lvz += __shfl_down_sync(0xffffffffu, lvz, o);
            avx += __shfl_down_sync(0xffffffffu, avx, o);
            avy += __shfl_down_sync(0xffffffffu, avy, o);
            avz += __shfl_down_sync(0xffffffffu, avz, o);
        }
        if (tid == 0) {
            float3 lv = qrot(qw0, -qx, -qy, -qz, make_float3(lvx, lvy, lvz));
            float3 av = qrot(qw0, -qx, -qy, -qz, make_float3(avx, avy, avz));
            float3 orb = { qc0.y * lv.z - qc0.z * lv.y,
                           qc0.z * lv.x - qc0.x * lv.z,
                           qc0.x * lv.y - qc0.y * lv.x };
            float e_w = qwgt[qi];
            const float inv_s2 = 0.70710678118654752440f;
            float* pp = &g_partial[(t * NQ + qi) * 6];
            pp[0] = e_w * (orb.x + av.x * inv_s2);
            pp[1] = e_w * (orb.y + av.y * inv_s2);
            pp[2] = e_w * (orb.z + av.z * inv_s2);
            pp[3] = e_w * lv.x;
            pp[4] = e_w * lv.y;
            pp[5] = e_w * lv.z;
        }
    }
}

// ---- deterministic final reduction over queries ------------------------------
__global__ void k_reduce(float* __restrict__ out) {
    int t = blockIdx.x, tid = threadIdx.x;
    int lane = tid & 31, wid = tid >> 5;
    float a[6];
    const float* pp = &g_partial[(t * NQ + tid) * 6];
#pragma unroll
    for (int j = 0; j < 6; j++) a[j] = pp[j];
#pragma unroll
    for (int j = 0; j < 6; j++) {
        for (int o = 16; o > 0; o >>= 1)
            a[j] += __shfl_down_sync(0xffffffffu, a[j], o);
    }
    __shared__ float sw[8][6];
    if (lane == 0) {
#pragma unroll
        for (int j = 0; j < 6; j++) sw[wid][j] = a[j];
    }
    __syncthreads();
    if (tid == 0) {
        float r[6] = {0, 0, 0, 0, 0, 0};
        for (int w2 = 0; w2 < 8; w2++)
            for (int j = 0; j < 6; j++) r[j] += sw[w2][j];
        out[t * 3 + 0] = r[0];
        out[t * 3 + 1] = r[1];
        out[t * 3 + 2] = r[2];
        out[NT * 3 + t * 3 + 0] = r[3];
        out[NT * 3 + t * 3 + 1] = r[4];
        out[NT * 3 + t * 3 + 2] = r[5];
    }
}

extern "C" void kernel_launch(void* const* d_in, const int* in_sizes, int n_in,
                              void* d_out, int out_size) {
    const float* T      = (const float*)d_in[0];
    const float* qwgt   = (const float*)d_in[1];
    const float* qfeat  = (const float*)d_in[2];
    const float* qcoord = (const float*)d_in[3];
    const float* nfeat  = (const float*)d_in[4];
    const float* ncoord = (const float*)d_in[5];
    const float* temb   = (const float*)d_in[6];
    const float* Wext   = (const float*)d_in[7];
    const float* Wrbf   = (const float*)d_in[8];
    const float* Wtime  = (const float*)d_in[9];
    const float* wp_lin = (const float*)d_in[10];
    const float* Wv_lin = (const float*)d_in[12];
    const float* wp_ang = (const float*)d_in[13];
    const float* Wv_ang = (const float*)d_in[15];
    const int*   qbatch = (const int*)d_in[16];
    const int*   nbatch = (const int*)d_in[17];
    float* out = (float*)d_out;

    k_pre<<<NNODE / PN + 64 + 1, 256>>>(nfeat, Wext, ncoord, temb, Wtime, nbatch,
                                        wp_lin, Wv_lin, wp_ang, Wv_ang);
    k_main<<<dim3(NQ, NT), 256>>>(T, qwgt, qfeat, qcoord, Wrbf, qbatch);
    k_reduce<<<NT, NQ>>>(out);
}

// round 15
// speedup vs baseline: 1.2741x; 1.0272x over previous
#include <cuda_runtime.h>
#include <math_constants.h>

#define NT 32
#define NQ 256
#define NNODE 8192
#define DD 128
#define CHN 32
#define KK 16
#define NBF 8
#define BB 4
#define CAP 4096
#define CANDCAP 192
#define PN 16
#define NGEMM (NNODE / PN)   // 512
#define NCOORD 128           // coord-pad blocks (128 threads each)

__device__ float g_nfext[NNODE * DD];
__device__ float g_cxp[BB * CAP], g_cyp[BB * CAP], g_czp[BB * CAP];  // padded SoA (INF pads)
__device__ float g_tf[DD];
__device__ int   g_range[BB + 1];
__device__ float g_coef[6 * CHN];
__device__ float g_partial[NT * NQ * 6];

static __device__ __forceinline__ float3 qrot(float w, float x, float y, float z, float3 v) {
    float uvx = y * v.z - z * v.y;
    float uvy = z * v.x - x * v.z;
    float uvz = x * v.y - y * v.x;
    float wx = y * uvz - z * uvy;
    float wy = z * uvx - x * uvz;
    float wz = x * uvy - y * uvx;
    float3 r;
    r.x = v.x + 2.f * (w * uvx + wx);
    r.y = v.y + 2.f * (w * uvy + wy);
    r.z = v.z + 2.f * (w * uvz + wz);
    return r;
}

// ---- fused precompute: 512 GEMM blocks (single wave) + coord/misc blocks -----
__global__ __launch_bounds__(128) void k_pre(
    const float* __restrict__ nf, const float* __restrict__ Wext,
    const float* __restrict__ ncoord,
    const float* __restrict__ te, const float* __restrict__ Wtime,
    const int* __restrict__ nbatch,
    const float* __restrict__ wp_lin, const float* __restrict__ Wv_lin,
    const float* __restrict__ wp_ang, const float* __restrict__ Wv_ang) {
    int tid = threadIdx.x;
    int blk = blockIdx.x;

    if (blk >= NGEMM) {
        if (blk < NGEMM + NCOORD) {
            // coord padding: 128 blocks x 128 slots = 16384
            int idx = (blk - NGEMM) * 128 + tid;
            int b = idx >> 12, i = idx & (CAP - 1);
            int lo = 0;
            if (b > 0) {
                int l = 0, h = NNODE;
                while (l < h) { int m2 = (l + h) >> 1; if (nbatch[m2] < b) l = m2 + 1; else h = m2; }
                lo = l;
            }
            int hi;
            {
                int l = lo, h = NNODE;
                while (l < h) { int m2 = (l + h) >> 1; if (nbatch[m2] < b + 1) l = m2 + 1; else h = m2; }
                hi = l;
            }
            int n = hi - lo;
            float vx = CUDART_INF_F, vy = CUDART_INF_F, vz = CUDART_INF_F;
            if (i < n) {
                vx = ncoord[(lo + i) * 3 + 0];
                vy = ncoord[(lo + i) * 3 + 1];
                vz = ncoord[(lo + i) * 3 + 2];
            }
            g_cxp[idx] = vx; g_cyp[idx] = vy; g_czp[idx] = vz;
        } else {
            // misc block (128 threads)
            {
                float acc = 0.f;
                for (int k = 0; k < DD; k++) acc = fmaf(te[k], Wtime[k * DD + tid], acc);
                g_tf[tid] = 1.f + acc;
            }
            if (tid <= BB) {
                int l = 0, h = NNODE;
                if (tid == BB) l = NNODE;
                else {
                    while (l < h) { int m2 = (l + h) >> 1; if (nbatch[m2] < tid) l = m2 + 1; else h = m2; }
                }
                g_range[tid] = l;
            }
            for (int item = tid; item < 192; item += 128) {
                int g = item / CHN, c = item % CHN;
                const float* wp = (g < 3) ? wp_lin : wp_ang;
                const float* Wv = (g < 3) ? Wv_lin : Wv_ang;
                int gg = g % 3;
                int wrow = gg * CHN + c;
                float s = 0.f;
                for (int o = 0; o < CHN; o++) s += Wv[wrow * CHN + o];
                g_coef[g * CHN + c] = wp[(2 + gg) * CHN + c] * s * (1.f / (float)CHN);
            }
        }
        return;
    }

    // GEMM blocks: 128 threads, PN=16 nodes, acc[4][4] (same chains as R14)
    __shared__ float sW[32 * DD];        // 16 KB k-tile of Wext
    __shared__ float snf[PN][33];        // padded node k-tile
    int b = blk;
    int cg = tid & 31;                   // col group (4 cols)
    int ng = tid >> 5;                   // 0..3 -> nodes ng*4..ng*4+3
    float acc[4][4];
#pragma unroll
    for (int i = 0; i < 4; i++)
#pragma unroll
        for (int j = 0; j < 4; j++) acc[i][j] = 0.f;
    for (int kt = 0; kt < DD; kt += 32) {
        // flat float4 copy: tile rows contiguous in Wext
        {
            const float4* src = (const float4*)(Wext + kt * DD);
            float4* dst = (float4*)sW;
#pragma unroll
            for (int v = 0; v < 8; v++) dst[tid + 128 * v] = src[tid + 128 * v];
        }
#pragma unroll
        for (int v = 0; v < 4; v++) {
            int idx = tid + 128 * v;     // 512 = 16 nodes x 32 k
            snf[idx >> 5][idx & 31] = nf[(b * PN + (idx >> 5)) * DD + kt + (idx & 31)];
        }
        __syncthreads();
#pragma unroll 8
        for (int kk = 0; kk < 32; kk++) {
            float4 w = *(const float4*)&sW[kk * DD + cg * 4];
            float a0 = snf[ng * 4 + 0][kk];
            float a1 = snf[ng * 4 + 1][kk];
            float a2 = snf[ng * 4 + 2][kk];
            float a3 = snf[ng * 4 + 3][kk];
            acc[0][0] = fmaf(a0, w.x, acc[0][0]); acc[0][1] = fmaf(a0, w.y, acc[0][1]);
            acc[0][2] = fmaf(a0, w.z, acc[0][2]); acc[0][3] = fmaf(a0, w.w, acc[0][3]);
            acc[1][0] = fmaf(a1, w.x, acc[1][0]); acc[1][1] = fmaf(a1, w.y, acc[1][1]);
            acc[1][2] = fmaf(a1, w.z, acc[1][2]); acc[1][3] = fmaf(a1, w.w, acc[1][3]);
            acc[2][0] = fmaf(a2, w.x, acc[2][0]); acc[2][1] = fmaf(a2, w.y, acc[2][1]);
            acc[2][2] = fmaf(a2, w.z, acc[2][2]); acc[2][3] = fmaf(a2, w.w, acc[2][3]);
            acc[3][0] = fmaf(a3, w.x, acc[3][0]); acc[3][1] = fmaf(a3, w.y, acc[3][1]);
            acc[3][2] = fmaf(a3, w.z, acc[3][2]); acc[3][3] = fmaf(a3, w.w, acc[3][3]);
        }
        __syncthreads();
    }
#pragma unroll
    for (int i = 0; i < 4; i++) {
        float4 o = { acc[i][0], acc[i][1], acc[i][2], acc[i][3] };
        *(float4*)&g_nfext[(b * PN + ng * 4 + i) * DD + cg * 4] = o;
    }
}

// ---- main: one block per (query, transform); 2nd-min prefilter select --------
__global__ __launch_bounds__(256, 6) void k_main(
    const float* __restrict__ T, const float* __restrict__ qwgt,
    const float* __restrict__ qf, const float* __restrict__ qcrd,
    const float* __restrict__ Wrbf, const int* __restrict__ qbatch) {
    __shared__ unsigned long long cand[CANDCAP];
    __shared__ float sw2[8];
    __shared__ float sM;
    __shared__ __align__(16) float srbf[KK * NBF];
    __shared__ float sfld2[2][DD];
    __shared__ float sfield[DD];
    __shared__ int ssel[KK];
    __shared__ float sd2sel[KK];
    __shared__ unsigned scnt;

    int qi = blockIdx.x, t = blockIdx.y, tid = threadIdx.x;
    int lane = tid & 31, wid = tid >> 5;

    int b = qbatch[qi];
    int lo = g_range[b];
    int n = g_range[b + 1] - lo;
    if (n > CAP) n = CAP;
    int n_pad = (n + 3) & ~3;
    float3 qc0 = { qcrd[qi * 3 + 0], qcrd[qi * 3 + 1], qcrd[qi * 3 + 2] };

    float qw0 = T[t * 7 + 0], qx = T[t * 7 + 1], qy = T[t * 7 + 2], qz = T[t * 7 + 3];
    float3 p = qrot(qw0, qx, qy, qz, qc0);
    p.x += T[t * 7 + 4]; p.y += T[t * 7 + 5]; p.z += T[t * 7 + 6];

    if (tid == 0) scnt = 0u;

    const float* cx = g_cxp + b * CAP;
    const float* cy = g_cyp + b * CAP;
    const float* cz = g_czp + b * CAP;

    // distance pass: first 2048 in registers; overflow recomputed later
    float d2v[8];
    float tmin = CUDART_INF_F;
#pragma unroll
    for (int g = 0; g < 2; g++) {
        int i0 = tid * 4 + 1024 * g;
        float4 X = *(const float4*)(cx + i0);
        float4 Y = *(const float4*)(cy + i0);
        float4 Z = *(const float4*)(cz + i0);
        float dx, dy, dz;
        dx = p.x - X.x; dy = p.y - Y.x; dz = p.z - Z.x;
        d2v[g * 4 + 0] = dx * dx + dy * dy + dz * dz;
        dx = p.x - X.y; dy = p.y - Y.y; dz = p.z - Z.y;
        d2v[g * 4 + 1] = dx * dx + dy * dy + dz * dz;
        dx = p.x - X.z; dy = p.y - Y.z; dz = p.z - Z.z;
        d2v[g * 4 + 2] = dx * dx + dy * dy + dz * dz;
        dx = p.x - X.w; dy = p.y - Y.w; dz = p.z - Z.w;
        d2v[g * 4 + 3] = dx * dx + dy * dy + dz * dz;
        tmin = fminf(tmin, fminf(fminf(d2v[g * 4 + 0], d2v[g * 4 + 1]),
                                 fminf(d2v[g * 4 + 2], d2v[g * 4 + 3])));
    }
    for (int i0 = 2048 + tid * 4; i0 < n_pad; i0 += 1024) {
        float4 X = *(const float4*)(cx + i0);
        float4 Y = *(const float4*)(cy + i0);
        float4 Z = *(const float4*)(cz + i0);
        float dx, dy, dz, d2;
        dx = p.x - X.x; dy = p.y - Y.x; dz = p.z - Z.x; d2 = dx * dx + dy * dy + dz * dz;
        tmin = fminf(tmin, d2);
        dx = p.x - X.y; dy = p.y - Y.y; dz = p.z - Z.y; d2 = dx * dx + dy * dy + dz * dz;
        tmin = fminf(tmin, d2);
        dx = p.x - X.z; dy = p.y - Y.z; dz = p.z - Z.z; d2 = dx * dx + dy * dy + dz * dz;
        tmin = fminf(tmin, d2);
        dx = p.x - X.w; dy = p.y - Y.w; dz = p.z - Z.w; d2 = dx * dx + dy * dy + dz * dz;
        tmin = fminf(tmin, d2);
    }

    // per-warp 2nd-smallest lane-min -> bound M (>=2 elements per warp <= it)
    {
        float v = tmin;
#pragma unroll
        for (int o = 16; o > 0; o >>= 1)
            v = fminf(v, __shfl_xor_sync(0xffffffffu, v, o));
        float m1 = v;
        unsigned bal = __ballot_sync(0xffffffffu, tmin == m1);
        int leader = __ffs(bal) - 1;
        float vv = (lane == leader) ? CUDART_INF_F : tmin;
#pragma unroll
        for (int o = 16; o > 0; o >>= 1)
            vv = fminf(vv, __shfl_xor_sync(0xffffffffu, vv, o));
        if (lane == 0) sw2[wid] = vv;
    }
    __syncthreads();
    if (tid == 0) {
        float M = sw2[0];
#pragma unroll
        for (int j = 1; j < 8; j++) M = fmaxf(M, sw2[j]);
        sM = M;
    }
    __syncthreads();
    float M = sM;

    // collect: ALL elements with d2 <= M (top-16 guaranteed inside)
#pragma unroll
    for (int j = 0; j < 8; j++) {
        if (d2v[j] <= M) {
            int i = tid * 4 + 1024 * (j >> 2) + (j & 3);
            unsigned pos = atomicAdd(&scnt, 1u);
            if (pos < CANDCAP)
                cand[pos] = ((unsigned long long)__float_as_uint(d2v[j]) << 32) | (unsigned)i;
        }
    }
    for (int i0 = 2048 + tid * 4; i0 < n_pad; i0 += 1024) {
        float4 X = *(const float4*)(cx + i0);
        float4 Y = *(const float4*)(cy + i0);
        float4 Z = *(const float4*)(cz + i0);
        float dvals[4];
        float dx, dy, dz;
        dx = p.x - X.x; dy = p.y - Y.x; dz = p.z - Z.x; dvals[0] = dx * dx + dy * dy + dz * dz;
        dx = p.x - X.y; dy = p.y - Y.y; dz = p.z - Z.y; dvals[1] = dx * dx + dy * dy + dz * dz;
        dx = p.x - X.z; dy = p.y - Y.z; dz = p.z - Z.z; dvals[2] = dx * dx + dy * dy + dz * dz;
        dx = p.x - X.w; dy = p.y - Y.w; dz = p.z - Z.w; dvals[3] = dx * dx + dy * dy + dz * dz;
#pragma unroll
        for (int k = 0; k < 4; k++) {
            if (dvals[k] <= M) {
                unsigned pos = atomicAdd(&scnt, 1u);
                if (pos < CANDCAP)
                    cand[pos] = ((unsigned long long)__float_as_uint(dvals[k]) << 32) | (unsigned)(i0 + k);
            }
        }
    }
    __syncthreads();

    // exact rank via LDS-broadcast compares (unique keys)
    int m = scnt < CANDCAP ? (int)scnt : CANDCAP;
    if (tid < m) {
        unsigned long long my = cand[tid];
        int r = 0;
        for (int j = 0; j < m; j++)
            r += (cand[j] < my);
        if (r < KK) {
            ssel[r] = (int)(unsigned)my;
            sd2sel[r] = __uint_as_float((unsigned)(my >> 32));
        }
    }
    __syncthreads();

    // rbf basis
    if (tid < KK * NBF) {
        int k = tid >> 3, bb2 = tid & 7;
        float d = sqrtf(fmaxf(sd2sel[k], 1e-12f));
        float e = d - (3.0f / 7.0f) * (float)bb2;
        srbf[tid] = expf(-4.f * e * e);
    }
    __syncthreads();

    // field: 256 threads, 8 k's each; Wrbf slice hoisted to registers
    {
        int d = tid & 127, h2 = tid >> 7;
        float W0 = Wrbf[0 * DD + d], W1 = Wrbf[1 * DD + d];
        float W2 = Wrbf[2 * DD + d], W3 = Wrbf[3 * DD + d];
        float W4 = Wrbf[4 * DD + d], W5 = Wrbf[5 * DD + d];
        float W6 = Wrbf[6 * DD + d], W7 = Wrbf[7 * DD + d];
        float acc = 0.f;
#pragma unroll
        for (int k2 = 0; k2 < 8; k2++) {
            int k = h2 * 8 + k2;
            float4 r0 = *(const float4*)&srbf[k * NBF];
            float4 r1 = *(const float4*)&srbf[k * NBF + 4];
            float coef = 0.f;
            coef = fmaf(r0.x, W0, coef);
            coef = fmaf(r0.y, W1, coef);
            coef = fmaf(r0.z, W2, coef);
            coef = fmaf(r0.w, W3, coef);
            coef = fmaf(r1.x, W4, coef);
            coef = fmaf(r1.y, W5, coef);
            coef = fmaf(r1.z, W6, coef);
            coef = fmaf(r1.w, W7, coef);
            acc = fmaf(coef, g_nfext[(lo + ssel[k]) * DD + d], acc);
        }
        sfld2[h2][d] = acc;
    }
    __syncthreads();
    if (tid < DD)
        sfield[tid] = (sfld2[0][tid] + sfld2[1][tid]) * g_tf[tid];
    __syncthreads();

    // dtp + per-(t,q) partial (warp0)
    if (tid < CHN) {
        float e_s  = qf[qi * DD + tid];
        float3 v0 = { qf[qi * DD + CHN + 3 * tid + 0],
                      qf[qi * DD + CHN + 3 * tid + 1],
                      qf[qi * DD + CHN + 3 * tid + 2] };
        float e_al = g_coef[tid];           float e_bl = g_coef[CHN + tid];     float e_el = g_coef[2 * CHN + tid];
        float e_aa = g_coef[3 * CHN + tid]; float e_ba = g_coef[4 * CHN + tid]; float e_ea = g_coef[5 * CHN + tid];
        float3 v = qrot(qw0, qx, qy, qz, v0);
        float ttv = sfield[tid];
        float3 u = { sfield[CHN + 3 * tid + 0], sfield[CHN + 3 * tid + 1], sfield[CHN + 3 * tid + 2] };
        float3 cr = { v.y * u.z - v.z * u.y, v.z * u.x - v.x * u.z, v.x * u.y - v.y * u.x };
        float lvx = e_al * e_s * u.x + e_bl * ttv * v.x + e_el * cr.x;
        float lvy = e_al * e_s * u.y + e_bl * ttv * v.y + e_el * cr.y;
        float lvz = e_al * e_s * u.z + e_bl * ttv * v.z + e_el * cr.z;
        float avx = e_aa * e_s * u.x + e_ba * ttv * v.x + e_ea * cr.x;
        float avy = e_aa * e_s * u.y + e_ba * ttv * v.y + e_ea * cr.y;
        float avz = e_aa * e_s * u.z + e_ba * ttv * v.z + e_ea * cr.z;
#pragma unroll
        for (int o = 16; o > 0; o >>= 1) {
            lvx += __shfl_down_sync(0xffffffffu, lvx, o);
            lvy += __shfl_down_sync(0xffffffffu, lvy, o);
            lvz += __shfl_down_sync(0xffffffffu, lvz, o);
            avx += __shfl_down_sync(0xffffffffu, avx, o);
            avy += __shfl_down_sync(0xffffffffu, avy, o);
            avz += __shfl_down_sync(0xffffffffu, avz, o);
        }
        if (tid == 0) {
            float3 lv = qrot(qw0, -qx, -qy, -qz, make_float3(lvx, lvy, lvz));
            float3 av = qrot(qw0, -qx, -qy, -qz, make_float3(avx, avy, avz));
            float3 orb = { qc0.y * lv.z - qc0.z * lv.y,
                           qc0.z * lv.x - qc0.x * lv.z,
                           qc0.x * lv.y - qc0.y * lv.x };
            float e_w = qwgt[qi];
            const float inv_s2 = 0.70710678118654752440f;
            float* pp = &g_partial[(t * NQ + qi) * 6];
            pp[0] = e_w * (orb.x + av.x * inv_s2);
            pp[1] = e_w * (orb.y + av.y * inv_s2);
            pp[2] = e_w * (orb.z + av.z * inv_s2);
            pp[3] = e_w * lv.x;
            pp[4] = e_w * lv.y;
            pp[5] = e_w * lv.z;
        }
    }
}

// ---- deterministic final reduction over queries ------------------------------
__global__ void k_reduce(float* __restrict__ out) {
    int t = blockIdx.x, tid = threadIdx.x;
    int lane = tid & 31, wid = tid >> 5;
    float a[6];
    const float* pp = &g_partial[(t * NQ + tid) * 6];
#pragma unroll
    for (int j = 0; j < 6; j++) a[j] = pp[j];
#pragma unroll
    for (int j = 0; j < 6; j++) {
        for (int o = 16; o > 0; o >>= 1)
            a[j] += __shfl_down_sync(0xffffffffu, a[j], o);
    }
    __shared__ float sw[8][6];
    if (lane == 0) {
#pragma unroll
        for (int j = 0; j < 6; j++) sw[wid][j] = a[j];
    }
    __syncthreads();
    if (tid == 0) {
        float r[6] = {0, 0, 0, 0, 0, 0};
        for (int w2 = 0; w2 < 8; w2++)
            for (int j = 0; j < 6; j++) r[j] += sw[w2][j];
        out[t * 3 + 0] = r[0];
        out[t * 3 + 1] = r[1];
        out[t * 3 + 2] = r[2];
        out[NT * 3 + t * 3 + 0] = r[3];
        out[NT * 3 + t * 3 + 1] = r[4];
        out[NT * 3 + t * 3 + 2] = r[5];
    }
}

extern "C" void kernel_launch(void* const* d_in, const int* in_sizes, int n_in,
                              void* d_out, int out_size) {
    const float* T      = (const float*)d_in[0];
    const float* qwgt   = (const float*)d_in[1];
    const float* qfeat  = (const float*)d_in[2];
    const float* qcoord = (const float*)d_in[3];
    const float* nfeat  = (const float*)d_in[4];
    const float* ncoord = (const float*)d_in[5];
    const float* temb   = (const float*)d_in[6];
    const float* Wext   = (const float*)d_in[7];
    const float* Wrbf   = (const float*)d_in[8];
    const float* Wtime  = (const float*)d_in[9];
    const float* wp_lin = (const float*)d_in[10];
    const float* Wv_lin = (const float*)d_in[12];
    const float* wp_ang = (const float*)d_in[13];
    const float* Wv_ang = (const float*)d_in[15];
    const int*   qbatch = (const int*)d_in[16];
    const int*   nbatch = (const int*)d_in[17];
    float* out = (float*)d_out;

    k_pre<<<NGEMM + NCOORD + 1, 128>>>(nfeat, Wext, ncoord, temb, Wtime, nbatch,
                                       wp_lin, Wv_lin, wp_ang, Wv_ang);
    k_main<<<dim3(NQ, NT), 256>>>(T, qwgt, qfeat, qcoord, Wrbf, qbatch);
    k_reduce<<<NT, NQ>>>(out);
}